// round 5
// baseline (speedup 1.0000x reference)
#include <cuda_runtime.h>

// Problem constants
#define PB 16384   // batch
#define PN 32      // keypoints
#define PK 16      // mixture components
// D = 3

#define MB  4      // samples per thread
#define TPB 128

__device__ __forceinline__ float ex2a(float x) {
    float r; asm("ex2.approx.ftz.f32 %0,%1;" : "=f"(r) : "f"(x)); return r;
}
__device__ __forceinline__ float rcpa(float x) {
    float r; asm("rcp.approx.ftz.f32 %0,%1;" : "=f"(r) : "f"(x)); return r;
}

// smem params [k][field][n]; field 0..2: -mean, 3..8: prec * (-0.5*log2e), 9: lc
__global__ void __launch_bounds__(TPB, 6) gmm_fused(const float* __restrict__ kps,
                                                    const float* __restrict__ means,
                                                    const float* __restrict__ covs,
                                                    const float* __restrict__ weights,
                                                    float* __restrict__ out) {
    __shared__ float sp[PK * 10 * PN];   // 20 KB

    int tid = threadIdx.x;

    // ---- per-block param precompute (512 items / 128 threads = 4 each) ----
    const float NH = -0.72134752044448170f;  // -(0.5 * log2 e)
#pragma unroll
    for (int it = 0; it < 4; it++) {
        int t = tid + it * TPB;
        int n = t & 31;
        int k = t >> 5;
        int nk = n * PK + k;

        const float* c = covs + nk * 9;
        float c00 = c[0], c01 = c[1], c02 = c[2];
        float c11 = c[4], c12 = c[5], c22 = c[8];

        float m00 = c11 * c22 - c12 * c12;
        float m01 = c02 * c12 - c01 * c22;
        float m02 = c01 * c12 - c02 * c11;
        float det = c00 * m00 + c01 * m01 + c02 * m02;
        float inv = NH / det;    // fold -0.5*log2e into the precision

        const float TWOPI3 = 248.05021344239853f;  // (2*pi)^3
        float lc = log2f(weights[nk]) - 0.5f * log2f(TWOPI3 * det);

        const float* mu = means + nk * 3;
        float* base = sp + k * 10 * PN + n;
        base[0 * PN] = -mu[0];
        base[1 * PN] = -mu[1];
        base[2 * PN] = -mu[2];
        base[3 * PN] = m00 * inv;
        base[4 * PN] = m01 * inv;
        base[5 * PN] = m02 * inv;
        base[6 * PN] = (c00 * c22 - c02 * c02) * inv;
        base[7 * PN] = (c01 * c02 - c00 * c12) * inv;
        base[8 * PN] = (c00 * c11 - c01 * c01) * inv;
        base[9 * PN] = lc;
    }
    __syncthreads();

    // ---- main compute ----
    int gtid = blockIdx.x * TPB + tid;
    int n  = gtid & 31;      // lane = keypoint -> coalesced I/O
    int bg = gtid >> 5;
    int b0 = bg * MB;

    float x[MB], y[MB], z[MB];
#pragma unroll
    for (int i = 0; i < MB; i++) {
        const float* p = kps + ((b0 + i) * PN + n) * 3;
        x[i] = p[0]; y[i] = p[1]; z[i] = p[2];
    }

    float pdf[MB], gx[MB], gy[MB], gz[MB];
#pragma unroll
    for (int i = 0; i < MB; i++) { pdf[i] = 0.0f; gx[i] = 0.0f; gy[i] = 0.0f; gz[i] = 0.0f; }

#pragma unroll 4
    for (int k = 0; k < PK; k++) {
        const float* pp = sp + k * 10 * PN + n;
        float nmx = pp[0 * PN];
        float nmy = pp[1 * PN];
        float nmz = pp[2 * PN];
        float q00 = pp[3 * PN];
        float q01 = pp[4 * PN];
        float q02 = pp[5 * PN];
        float q11 = pp[6 * PN];
        float q12 = pp[7 * PN];
        float q22 = pp[8 * PN];
        float lc  = pp[9 * PN];

#pragma unroll
        for (int i = 0; i < MB; i++) {
            float d0 = x[i] + nmx;
            float d1 = y[i] + nmy;
            float d2 = z[i] + nmz;
            // pd = (-0.5*log2e) * Sigma^{-1}(x-mu)
            float pd0 = fmaf(q00, d0, fmaf(q01, d1, q02 * d2));
            float pd1 = fmaf(q01, d0, fmaf(q11, d1, q12 * d2));
            float pd2 = fmaf(q02, d0, fmaf(q12, d1, q22 * d2));
            // earg = (-0.5*log2e)*maha + lc
            float earg = fmaf(pd0, d0, fmaf(pd1, d1, fmaf(pd2, d2, lc)));
            float e = ex2a(earg);
            pdf[i] += e;
            gx[i] = fmaf(e, pd0, gx[i]);
            gy[i] = fmaf(e, pd1, gy[i]);
            gz[i] = fmaf(e, pd2, gz[i]);
        }
    }

    // ---- epilogue ----
    // gacc = (0.5*log2e) * grad_true (positive multiple -> same direction)
    // (log2e/1100)/(0.5*log2e) = 1/550 exactly -> mag = 2^(5*log2e - |gacc|/550)
    const float L2E_OVER_TAU = 0.19235933878519513f;   // log2e / 7.5
    const float MAG_C0 = 7.2134752044448170f;          // 5 * log2 e
    const float MAG_C1 = -1.0f / 550.0f;
    float* out_grad = out + (size_t)PB * PN * 3;

#pragma unroll
    for (int i = 0; i < MB; i++) {
        int b = b0 + i;
        float u = ex2a((40.0f - pdf[i]) * L2E_OVER_TAU);
        float s = rcpa(1.0f + u);

        float s2 = fmaf(gx[i], gx[i], fmaf(gy[i], gy[i], gz[i] * gz[i]));
        float rinv = rsqrtf(s2);
        float gs = s2 * rinv;                       // |gacc|
        float mag = ex2a(fmaf(gs, MAG_C1, MAG_C0));
        float scale = rinv * mag;                   // ETA=1; sign correct

        float* od = out + ((size_t)b * PN + n) * 3;
        od[0] = s; od[1] = s; od[2] = s;
        float* og = out_grad + ((size_t)b * PN + n) * 3;
        og[0] = gx[i] * scale;
        og[1] = gy[i] * scale;
        og[2] = gz[i] * scale;
    }
}

extern "C" void kernel_launch(void* const* d_in, const int* in_sizes, int n_in,
                              void* d_out, int out_size) {
    const float* kps     = (const float*)d_in[0];
    const float* means   = (const float*)d_in[1];
    const float* covs    = (const float*)d_in[2];
    const float* weights = (const float*)d_in[3];
    float* out = (float*)d_out;

    int total_threads = (PB / MB) * PN;       // 131072
    gmm_fused<<<total_threads / TPB, TPB>>>(kps, means, covs, weights, out);
}

// round 7
// speedup vs baseline: 1.0026x; 1.0026x over previous
#include <cuda_runtime.h>

// Problem constants
#define PB 16384   // batch
#define PN 32      // keypoints
#define PK 16      // mixture components
#define KH 8       // components per thread (K split 2 ways)
#define MB 8       // samples per thread
#define TPB 128

#define KSTRIDE 322          // words per k in param array (320 + 2 pad: 8*322 % 32 == 16)
#define PBYTES  (PK * KSTRIDE)

// params, layout word index: k*KSTRIDE + field*32 + n
// field 0..2: -mean ; 3..8: precision * (-0.5*log2e) ; 9: lc
__device__ float g_params[PBYTES];

__global__ void precompute_params(const float* __restrict__ means,
                                  const float* __restrict__ covs,
                                  const float* __restrict__ weights) {
    int t = threadIdx.x;
    if (t >= PN * PK) return;
    int n = t & 31;
    int k = t >> 5;
    int nk = n * PK + k;

    const float* c = covs + nk * 9;
    float c00 = c[0], c01 = c[1], c02 = c[2];
    float c11 = c[4], c12 = c[5], c22 = c[8];

    float m00 = c11 * c22 - c12 * c12;
    float m01 = c02 * c12 - c01 * c22;
    float m02 = c01 * c12 - c02 * c11;
    float det = c00 * m00 + c01 * m01 + c02 * m02;
    const float NH = -0.72134752044448170f;   // -(0.5*log2 e), folded into precision
    float inv = NH / det;

    const float TWOPI3 = 248.05021344239853f; // (2*pi)^3
    float lc = log2f(weights[nk]) - 0.5f * log2f(TWOPI3 * det);

    const float* mu = means + nk * 3;
    float* base = g_params + k * KSTRIDE + n;
    base[0 * 32] = -mu[0];
    base[1 * 32] = -mu[1];
    base[2 * 32] = -mu[2];
    base[3 * 32] = m00 * inv;
    base[4 * 32] = m01 * inv;
    base[5 * 32] = m02 * inv;
    base[6 * 32] = (c00 * c22 - c02 * c02) * inv;
    base[7 * 32] = (c01 * c02 - c00 * c12) * inv;
    base[8 * 32] = (c00 * c11 - c01 * c01) * inv;
    base[9 * 32] = lc;
}

__device__ __forceinline__ float ex2a(float x) {
    float r; asm("ex2.approx.ftz.f32 %0,%1;" : "=f"(r) : "f"(x)); return r;
}
__device__ __forceinline__ float rcpa(float x) {
    float r; asm("rcp.approx.ftz.f32 %0,%1;" : "=f"(r) : "f"(x)); return r;
}

__global__ void __launch_bounds__(TPB, 6) gmm_main(const float* __restrict__ kps,
                                                   float* __restrict__ out) {
    __shared__ float sp[PBYTES];   // ~20.6 KB

    int tid = threadIdx.x;
    for (int i = tid; i < PBYTES; i += TPB) sp[i] = g_params[i];
    __syncthreads();

    // index decode: lane = khalf*16 + n16 ; warp handles 16 consecutive n, both k-halves
    int gtid = blockIdx.x * TPB + tid;
    int lane = gtid & 31;
    int n16  = lane & 15;
    int kh   = lane >> 4;          // which half of K this thread computes
    int rest = gtid >> 5;
    int nhi  = rest & 1;
    int n    = nhi * 16 + n16;
    int bg   = rest >> 1;          // 0 .. PB/MB-1
    int b0   = bg * MB;

    float x[MB], y[MB], z[MB];
#pragma unroll
    for (int i = 0; i < MB; i++) {
        const float* p = kps + ((b0 + i) * PN + n) * 3;
        x[i] = p[0]; y[i] = p[1]; z[i] = p[2];
    }

    float pdf[MB], gx[MB], gy[MB], gz[MB];
#pragma unroll
    for (int i = 0; i < MB; i++) { pdf[i] = 0.0f; gx[i] = 0.0f; gy[i] = 0.0f; gz[i] = 0.0f; }

    const float* base = sp + kh * (KH * KSTRIDE) + n;

#pragma unroll 2
    for (int j = 0; j < KH; j++) {
        const float* pp = base + j * KSTRIDE;
        float nmx = pp[0 * 32];
        float nmy = pp[1 * 32];
        float nmz = pp[2 * 32];
        float q00 = pp[3 * 32];
        float q01 = pp[4 * 32];
        float q02 = pp[5 * 32];
        float q11 = pp[6 * 32];
        float q12 = pp[7 * 32];
        float q22 = pp[8 * 32];
        float lc  = pp[9 * 32];

#pragma unroll
        for (int i = 0; i < MB; i++) {
            float d0 = x[i] + nmx;
            float d1 = y[i] + nmy;
            float d2 = z[i] + nmz;
            // pd = (-0.5*log2e) * Sigma^{-1}(x-mu)
            float pd0 = fmaf(q00, d0, fmaf(q01, d1, q02 * d2));
            float pd1 = fmaf(q01, d0, fmaf(q11, d1, q12 * d2));
            float pd2 = fmaf(q02, d0, fmaf(q12, d1, q22 * d2));
            float earg = fmaf(pd0, d0, fmaf(pd1, d1, fmaf(pd2, d2, lc)));
            float e = ex2a(earg);
            pdf[i] += e;
            gx[i] = fmaf(e, pd0, gx[i]);
            gy[i] = fmaf(e, pd1, gy[i]);
            gz[i] = fmaf(e, pd2, gz[i]);
        }
    }

    // combine the two k-halves: partner lane is lane ^ 16 (same b,n)
#pragma unroll
    for (int i = 0; i < MB; i++) {
        pdf[i] += __shfl_xor_sync(0xFFFFFFFFu, pdf[i], 16);
        gx[i]  += __shfl_xor_sync(0xFFFFFFFFu, gx[i],  16);
        gy[i]  += __shfl_xor_sync(0xFFFFFFFFu, gy[i],  16);
        gz[i]  += __shfl_xor_sync(0xFFFFFFFFu, gz[i],  16);
    }

    // epilogue: gacc = (0.5*log2e)*grad_true (positive multiple);
    // (log2e/1100)/(0.5*log2e) = 1/550 -> mag = 2^(5*log2e - |gacc|/550)
    const float L2E_OVER_TAU = 0.19235933878519513f;  // log2e / 7.5
    const float MAG_C0 = 7.2134752044448170f;         // 5 * log2 e
    const float MAG_C1 = -1.0f / 550.0f;
    float* out_grad = out + (size_t)PB * PN * 3;

#pragma unroll
    for (int i = 0; i < MB; i++) {
        int b = b0 + i;
        if (kh == 0) {
            // density sigmoid, written by lanes 0..15 (contiguous 192B)
            float u = ex2a((40.0f - pdf[i]) * L2E_OVER_TAU);
            float s = rcpa(1.0f + u);
            float* od = out + ((size_t)b * PN + n) * 3;
            od[0] = s; od[1] = s; od[2] = s;
        } else {
            // gradient, written by lanes 16..31 (contiguous 192B)
            float s2 = fmaf(gx[i], gx[i], fmaf(gy[i], gy[i], gz[i] * gz[i]));
            float rinv = rsqrtf(s2);
            float gs = s2 * rinv;                    // |gacc|
            float mag = ex2a(fmaf(gs, MAG_C1, MAG_C0));
            float scale = rinv * mag;                // ETA=1; sign correct
            float* og = out_grad + ((size_t)b * PN + n) * 3;
            og[0] = gx[i] * scale;
            og[1] = gy[i] * scale;
            og[2] = gz[i] * scale;
        }
    }
}

extern "C" void kernel_launch(void* const* d_in, const int* in_sizes, int n_in,
                              void* d_out, int out_size) {
    const float* kps     = (const float*)d_in[0];
    const float* means   = (const float*)d_in[1];
    const float* covs    = (const float*)d_in[2];
    const float* weights = (const float*)d_in[3];
    float* out = (float*)d_out;

    precompute_params<<<1, 512>>>(means, covs, weights);

    int total_threads = (PB / MB) * PN * 2;     // 131072 (k split 2-way)
    gmm_main<<<total_threads / TPB, TPB>>>(kps, out);
}

// round 8
// speedup vs baseline: 1.1810x; 1.1778x over previous
#include <cuda_runtime.h>

// Problem constants
#define PB 16384   // batch
#define PN 32      // keypoints
#define PK 16      // mixture components
#define KH 8       // components per thread (K split 2 ways)
#define MB 8       // samples per thread
#define TPB 256

// params, layout word index: k*(10*PN) + field*PN + n
// field 0..2: -mean ; 3..8: precision * (-0.5*log2e) ; 9: lc
__device__ float g_params[PK * 10 * PN];

__global__ void precompute_params(const float* __restrict__ means,
                                  const float* __restrict__ covs,
                                  const float* __restrict__ weights) {
    int t = threadIdx.x;
    if (t >= PN * PK) return;
    int n = t & 31;
    int k = t >> 5;
    int nk = n * PK + k;

    const float* c = covs + nk * 9;
    float c00 = c[0], c01 = c[1], c02 = c[2];
    float c11 = c[4], c12 = c[5], c22 = c[8];

    float m00 = c11 * c22 - c12 * c12;
    float m01 = c02 * c12 - c01 * c22;
    float m02 = c01 * c12 - c02 * c11;
    float det = c00 * m00 + c01 * m01 + c02 * m02;
    const float NH = -0.72134752044448170f;   // -(0.5*log2 e), folded into precision
    float inv = NH / det;

    const float TWOPI3 = 248.05021344239853f; // (2*pi)^3
    float lc = log2f(weights[nk]) - 0.5f * log2f(TWOPI3 * det);

    const float* mu = means + nk * 3;
    float* base = g_params + k * 10 * PN + n;
    base[0 * PN] = -mu[0];
    base[1 * PN] = -mu[1];
    base[2 * PN] = -mu[2];
    base[3 * PN] = m00 * inv;
    base[4 * PN] = m01 * inv;
    base[5 * PN] = m02 * inv;
    base[6 * PN] = (c00 * c22 - c02 * c02) * inv;
    base[7 * PN] = (c01 * c02 - c00 * c12) * inv;
    base[8 * PN] = (c00 * c11 - c01 * c01) * inv;
    base[9 * PN] = lc;
}

__device__ __forceinline__ float ex2a(float x) {
    float r; asm("ex2.approx.ftz.f32 %0,%1;" : "=f"(r) : "f"(x)); return r;
}
__device__ __forceinline__ float rcpa(float x) {
    float r; asm("rcp.approx.ftz.f32 %0,%1;" : "=f"(r) : "f"(x)); return r;
}

// NO launch_bounds reg cap: R5/R7 showed capped regs -> spills -> regression.
__global__ void gmm_main(const float* __restrict__ kps,
                         float* __restrict__ out) {
    // index decode: lane = khalf*16 + n16 ; warp covers 16 consecutive n, both k-halves
    int gtid = blockIdx.x * TPB + threadIdx.x;
    int lane = gtid & 31;
    int n16  = lane & 15;
    int kh   = lane >> 4;          // which half of K this thread computes
    int rest = gtid >> 5;
    int nhi  = rest & 1;
    int n    = nhi * 16 + n16;
    int bg   = rest >> 1;          // 0 .. PB/MB-1
    int b0   = bg * MB;

    float x[MB], y[MB], z[MB];
#pragma unroll
    for (int i = 0; i < MB; i++) {
        const float* p = kps + ((b0 + i) * PN + n) * 3;
        x[i] = p[0]; y[i] = p[1]; z[i] = p[2];
    }

    float pdf[MB], gx[MB], gy[MB], gz[MB];
#pragma unroll
    for (int i = 0; i < MB; i++) { pdf[i] = 0.0f; gx[i] = 0.0f; gy[i] = 0.0f; gz[i] = 0.0f; }

    const float* base = g_params + kh * (KH * 10 * PN) + n;

#pragma unroll 2
    for (int j = 0; j < KH; j++) {
        const float* pp = base + j * (10 * PN);
        float nmx = __ldg(pp + 0 * PN);
        float nmy = __ldg(pp + 1 * PN);
        float nmz = __ldg(pp + 2 * PN);
        float q00 = __ldg(pp + 3 * PN);
        float q01 = __ldg(pp + 4 * PN);
        float q02 = __ldg(pp + 5 * PN);
        float q11 = __ldg(pp + 6 * PN);
        float q12 = __ldg(pp + 7 * PN);
        float q22 = __ldg(pp + 8 * PN);
        float lc  = __ldg(pp + 9 * PN);

#pragma unroll
        for (int i = 0; i < MB; i++) {
            float d0 = x[i] + nmx;
            float d1 = y[i] + nmy;
            float d2 = z[i] + nmz;
            // pd = (-0.5*log2e) * Sigma^{-1}(x-mu)
            float pd0 = fmaf(q00, d0, fmaf(q01, d1, q02 * d2));
            float pd1 = fmaf(q01, d0, fmaf(q11, d1, q12 * d2));
            float pd2 = fmaf(q02, d0, fmaf(q12, d1, q22 * d2));
            float earg = fmaf(pd0, d0, fmaf(pd1, d1, fmaf(pd2, d2, lc)));
            float e = ex2a(earg);
            pdf[i] += e;
            gx[i] = fmaf(e, pd0, gx[i]);
            gy[i] = fmaf(e, pd1, gy[i]);
            gz[i] = fmaf(e, pd2, gz[i]);
        }
    }

    // combine the two k-halves: partner lane is lane ^ 16 (same b,n)
#pragma unroll
    for (int i = 0; i < MB; i++) {
        pdf[i] += __shfl_xor_sync(0xFFFFFFFFu, pdf[i], 16);
        gx[i]  += __shfl_xor_sync(0xFFFFFFFFu, gx[i],  16);
        gy[i]  += __shfl_xor_sync(0xFFFFFFFFu, gy[i],  16);
        gz[i]  += __shfl_xor_sync(0xFFFFFFFFu, gz[i],  16);
    }

    // epilogue: gacc = (0.5*log2e)*grad_true (positive multiple);
    // (log2e/1100)/(0.5*log2e) = 1/550 -> mag = 2^(5*log2e - |gacc|/550)
    const float L2E_OVER_TAU = 0.19235933878519513f;  // log2e / 7.5
    const float MAG_C0 = 7.2134752044448170f;         // 5 * log2 e
    const float MAG_C1 = -1.0f / 550.0f;
    float* out_grad = out + (size_t)PB * PN * 3;

    if (kh == 0) {
        // density sigmoid, lanes 0..15: contiguous 192B per (warp,i)
#pragma unroll
        for (int i = 0; i < MB; i++) {
            int b = b0 + i;
            float u = ex2a((40.0f - pdf[i]) * L2E_OVER_TAU);
            float s = rcpa(1.0f + u);
            float* od = out + ((size_t)b * PN + n) * 3;
            od[0] = s; od[1] = s; od[2] = s;
        }
    } else {
        // gradient, lanes 16..31: contiguous 192B per (warp,i)
#pragma unroll
        for (int i = 0; i < MB; i++) {
            int b = b0 + i;
            float s2 = fmaf(gx[i], gx[i], fmaf(gy[i], gy[i], gz[i] * gz[i]));
            float rinv = rsqrtf(s2);
            float gs = s2 * rinv;                    // |gacc|
            float mag = ex2a(fmaf(gs, MAG_C1, MAG_C0));
            float scale = rinv * mag;                // ETA=1; sign correct
            float* og = out_grad + ((size_t)b * PN + n) * 3;
            og[0] = gx[i] * scale;
            og[1] = gy[i] * scale;
            og[2] = gz[i] * scale;
        }
    }
}

extern "C" void kernel_launch(void* const* d_in, const int* in_sizes, int n_in,
                              void* d_out, int out_size) {
    const float* kps     = (const float*)d_in[0];
    const float* means   = (const float*)d_in[1];
    const float* covs    = (const float*)d_in[2];
    const float* weights = (const float*)d_in[3];
    float* out = (float*)d_out;

    precompute_params<<<1, 512>>>(means, covs, weights);

    int total_threads = (PB / MB) * PN * 2;     // 131072 (k split 2-way)
    gmm_main<<<total_threads / TPB, TPB>>>(kps, out);
}

// round 9
// speedup vs baseline: 1.3142x; 1.1128x over previous
#include <cuda_runtime.h>

// Problem constants
#define PB 16384   // batch
#define PN 32      // keypoints
#define PK 16      // mixture components
#define KH 8       // components per thread (K split 2 ways)
#define MB 4       // samples per thread
#define TPB 128

// params, layout word index: k*(10*PN) + field*PN + n
// field 0..2: -mean ; 3..8: precision * (-0.5*log2e) ; 9: lc
__device__ float g_params[PK * 10 * PN];

__global__ void precompute_params(const float* __restrict__ means,
                                  const float* __restrict__ covs,
                                  const float* __restrict__ weights) {
    int t = blockIdx.x * 256 + threadIdx.x;
    if (t >= PN * PK) return;
    int n = t & 31;
    int k = t >> 5;
    int nk = n * PK + k;

    const float* c = covs + nk * 9;
    float c00 = c[0], c01 = c[1], c02 = c[2];
    float c11 = c[4], c12 = c[5], c22 = c[8];

    float m00 = c11 * c22 - c12 * c12;
    float m01 = c02 * c12 - c01 * c22;
    float m02 = c01 * c12 - c02 * c11;
    float det = c00 * m00 + c01 * m01 + c02 * m02;
    const float NH = -0.72134752044448170f;   // -(0.5*log2 e), folded into precision
    float inv = NH / det;

    const float TWOPI3 = 248.05021344239853f; // (2*pi)^3
    float lc = log2f(weights[nk]) - 0.5f * log2f(TWOPI3 * det);

    const float* mu = means + nk * 3;
    float* base = g_params + k * 10 * PN + n;
    base[0 * PN] = -mu[0];
    base[1 * PN] = -mu[1];
    base[2 * PN] = -mu[2];
    base[3 * PN] = m00 * inv;
    base[4 * PN] = m01 * inv;
    base[5 * PN] = m02 * inv;
    base[6 * PN] = (c00 * c22 - c02 * c02) * inv;
    base[7 * PN] = (c01 * c02 - c00 * c12) * inv;
    base[8 * PN] = (c00 * c11 - c01 * c01) * inv;
    base[9 * PN] = lc;
}

__device__ __forceinline__ float ex2a(float x) {
    float r; asm("ex2.approx.ftz.f32 %0,%1;" : "=f"(r) : "f"(x)); return r;
}
__device__ __forceinline__ float rcpa(float x) {
    float r; asm("rcp.approx.ftz.f32 %0,%1;" : "=f"(r) : "f"(x)); return r;
}

// NO launch_bounds reg cap (R5/R7: caps -> spills -> regression).
__global__ void gmm_main(const float* __restrict__ kps,
                         float* __restrict__ out) {
    // index decode: lane = khalf*16 + n16 ; warp covers 16 consecutive n, both k-halves
    int gtid = blockIdx.x * TPB + threadIdx.x;
    int lane = gtid & 31;
    int n16  = lane & 15;
    int kh   = lane >> 4;          // which half of K this thread computes
    int rest = gtid >> 5;
    int nhi  = rest & 1;
    int n    = nhi * 16 + n16;
    int bg   = rest >> 1;          // 0 .. PB/MB-1
    int b0   = bg * MB;

    float x[MB], y[MB], z[MB];
#pragma unroll
    for (int i = 0; i < MB; i++) {
        const float* p = kps + ((b0 + i) * PN + n) * 3;
        x[i] = p[0]; y[i] = p[1]; z[i] = p[2];
    }

    float pdf[MB], gx[MB], gy[MB], gz[MB];
#pragma unroll
    for (int i = 0; i < MB; i++) { pdf[i] = 0.0f; gx[i] = 0.0f; gy[i] = 0.0f; gz[i] = 0.0f; }

    const float* base = g_params + kh * (KH * 10 * PN) + n;

#pragma unroll 2
    for (int j = 0; j < KH; j++) {
        const float* pp = base + j * (10 * PN);
        float nmx = __ldg(pp + 0 * PN);
        float nmy = __ldg(pp + 1 * PN);
        float nmz = __ldg(pp + 2 * PN);
        float q00 = __ldg(pp + 3 * PN);
        float q01 = __ldg(pp + 4 * PN);
        float q02 = __ldg(pp + 5 * PN);
        float q11 = __ldg(pp + 6 * PN);
        float q12 = __ldg(pp + 7 * PN);
        float q22 = __ldg(pp + 8 * PN);
        float lc  = __ldg(pp + 9 * PN);

#pragma unroll
        for (int i = 0; i < MB; i++) {
            float d0 = x[i] + nmx;
            float d1 = y[i] + nmy;
            float d2 = z[i] + nmz;
            // pd = (-0.5*log2e) * Sigma^{-1}(x-mu)
            float pd0 = fmaf(q00, d0, fmaf(q01, d1, q02 * d2));
            float pd1 = fmaf(q01, d0, fmaf(q11, d1, q12 * d2));
            float pd2 = fmaf(q02, d0, fmaf(q12, d1, q22 * d2));
            float earg = fmaf(pd0, d0, fmaf(pd1, d1, fmaf(pd2, d2, lc)));
            float e = ex2a(earg);
            pdf[i] += e;
            gx[i] = fmaf(e, pd0, gx[i]);
            gy[i] = fmaf(e, pd1, gy[i]);
            gz[i] = fmaf(e, pd2, gz[i]);
        }
    }

    // combine the two k-halves: partner lane is lane ^ 16 (same b,n)
#pragma unroll
    for (int i = 0; i < MB; i++) {
        pdf[i] += __shfl_xor_sync(0xFFFFFFFFu, pdf[i], 16);
        gx[i]  += __shfl_xor_sync(0xFFFFFFFFu, gx[i],  16);
        gy[i]  += __shfl_xor_sync(0xFFFFFFFFu, gy[i],  16);
        gz[i]  += __shfl_xor_sync(0xFFFFFFFFu, gz[i],  16);
    }

    // epilogue: gacc = (0.5*log2e)*grad_true (positive multiple);
    // (log2e/1100)/(0.5*log2e) = 1/550 -> mag = 2^(5*log2e - |gacc|/550)
    const float L2E_OVER_TAU = 0.19235933878519513f;  // log2e / 7.5
    const float MAG_C0 = 7.2134752044448170f;         // 5 * log2 e
    const float MAG_C1 = -1.0f / 550.0f;
    float* out_grad = out + (size_t)PB * PN * 3;

    if (kh == 0) {
        // density sigmoid, lanes 0..15: contiguous 192B per (warp,i)
#pragma unroll
        for (int i = 0; i < MB; i++) {
            int b = b0 + i;
            float u = ex2a((40.0f - pdf[i]) * L2E_OVER_TAU);
            float s = rcpa(1.0f + u);
            float* od = out + ((size_t)b * PN + n) * 3;
            od[0] = s; od[1] = s; od[2] = s;
        }
    } else {
        // gradient, lanes 16..31: contiguous 192B per (warp,i)
#pragma unroll
        for (int i = 0; i < MB; i++) {
            int b = b0 + i;
            float s2 = fmaf(gx[i], gx[i], fmaf(gy[i], gy[i], gz[i] * gz[i]));
            float rinv = rsqrtf(s2);
            float gs = s2 * rinv;                    // |gacc|
            float mag = ex2a(fmaf(gs, MAG_C1, MAG_C0));
            float scale = rinv * mag;                // ETA=1; sign correct
            float* og = out_grad + ((size_t)b * PN + n) * 3;
            og[0] = gx[i] * scale;
            og[1] = gy[i] * scale;
            og[2] = gz[i] * scale;
        }
    }
}

extern "C" void kernel_launch(void* const* d_in, const int* in_sizes, int n_in,
                              void* d_out, int out_size) {
    const float* kps     = (const float*)d_in[0];
    const float* means   = (const float*)d_in[1];
    const float* covs    = (const float*)d_in[2];
    const float* weights = (const float*)d_in[3];
    float* out = (float*)d_out;

    precompute_params<<<2, 256>>>(means, covs, weights);

    int total_threads = (PB / MB) * PN * 2;     // 262144 (k split 2-way)
    gmm_main<<<total_threads / TPB, TPB>>>(kps, out);
}

// round 10
// speedup vs baseline: 1.4123x; 1.0746x over previous
#include <cuda_runtime.h>

// Problem constants
#define PB 16384   // batch
#define PN 32      // keypoints
#define PK 16      // mixture components
#define KH 8       // components per thread (K split 2 ways)
#define MB 4       // samples per thread
#define TPB 128

// Packed per-(n,k) params, SoA over n within each k, idx = k*32 + n:
//  g_pa: (-mx, -my, -mz, q00)
//  g_pb: (q01, q02, q11, q12)
//  g_pc: (q22, lc)
// q = precision * (-0.5*log2e), lc = log2(w) - 0.5*log2((2pi)^3 det)
__device__ float4 g_pa[PK * PN];
__device__ float4 g_pb[PK * PN];
__device__ float2 g_pc[PK * PN];

__global__ void precompute_params(const float* __restrict__ means,
                                  const float* __restrict__ covs,
                                  const float* __restrict__ weights) {
    int t = blockIdx.x * 256 + threadIdx.x;
    if (t >= PN * PK) return;
    int n = t & 31;
    int k = t >> 5;
    int nk = n * PK + k;

    const float* c = covs + nk * 9;
    float c00 = c[0], c01 = c[1], c02 = c[2];
    float c11 = c[4], c12 = c[5], c22 = c[8];

    float m00 = c11 * c22 - c12 * c12;
    float m01 = c02 * c12 - c01 * c22;
    float m02 = c01 * c12 - c02 * c11;
    float det = c00 * m00 + c01 * m01 + c02 * m02;
    const float NH = -0.72134752044448170f;   // -(0.5*log2 e), folded into precision
    float inv = NH / det;

    const float TWOPI3 = 248.05021344239853f; // (2*pi)^3
    float lc = log2f(weights[nk]) - 0.5f * log2f(TWOPI3 * det);

    const float* mu = means + nk * 3;
    int idx = k * PN + n;
    g_pa[idx] = make_float4(-mu[0], -mu[1], -mu[2], m00 * inv);
    g_pb[idx] = make_float4(m01 * inv, m02 * inv,
                            (c00 * c22 - c02 * c02) * inv,
                            (c01 * c02 - c00 * c12) * inv);
    g_pc[idx] = make_float2((c00 * c11 - c01 * c01) * inv, lc);
}

__device__ __forceinline__ float ex2a(float x) {
    float r; asm("ex2.approx.ftz.f32 %0,%1;" : "=f"(r) : "f"(x)); return r;
}
__device__ __forceinline__ float rcpa(float x) {
    float r; asm("rcp.approx.ftz.f32 %0,%1;" : "=f"(r) : "f"(x)); return r;
}

// NO launch_bounds reg cap (R5/R7: caps -> spills -> regression).
__global__ void gmm_main(const float* __restrict__ kps,
                         float* __restrict__ out) {
    // index decode: lane = khalf*16 + n16 ; warp covers 16 consecutive n, both k-halves
    int gtid = blockIdx.x * TPB + threadIdx.x;
    int lane = gtid & 31;
    int n16  = lane & 15;
    int kh   = lane >> 4;          // which half of K this thread computes
    int rest = gtid >> 5;
    int nhi  = rest & 1;
    int n    = nhi * 16 + n16;
    int bg   = rest >> 1;          // 0 .. PB/MB-1
    int b0   = bg * MB;

    float x[MB], y[MB], z[MB];
#pragma unroll
    for (int i = 0; i < MB; i++) {
        const float* p = kps + ((b0 + i) * PN + n) * 3;
        x[i] = p[0]; y[i] = p[1]; z[i] = p[2];
    }

    float pdf[MB], gx[MB], gy[MB], gz[MB];
#pragma unroll
    for (int i = 0; i < MB; i++) { pdf[i] = 0.0f; gx[i] = 0.0f; gy[i] = 0.0f; gz[i] = 0.0f; }

    int pbase = kh * (KH * PN) + n;

#pragma unroll 2
    for (int j = 0; j < KH; j++) {
        int idx = pbase + j * PN;
        float4 pa = __ldg(g_pa + idx);   // -mx, -my, -mz, q00
        float4 pb = __ldg(g_pb + idx);   // q01, q02, q11, q12
        float2 pc = __ldg(g_pc + idx);   // q22, lc

#pragma unroll
        for (int i = 0; i < MB; i++) {
            float d0 = x[i] + pa.x;
            float d1 = y[i] + pa.y;
            float d2 = z[i] + pa.z;
            // pd = (-0.5*log2e) * Sigma^{-1}(x-mu)
            float pd0 = fmaf(pa.w, d0, fmaf(pb.x, d1, pb.y * d2));
            float pd1 = fmaf(pb.x, d0, fmaf(pb.z, d1, pb.w * d2));
            float pd2 = fmaf(pb.y, d0, fmaf(pb.w, d1, pc.x * d2));
            float earg = fmaf(pd0, d0, fmaf(pd1, d1, fmaf(pd2, d2, pc.y)));
            float e = ex2a(earg);
            pdf[i] += e;
            gx[i] = fmaf(e, pd0, gx[i]);
            gy[i] = fmaf(e, pd1, gy[i]);
            gz[i] = fmaf(e, pd2, gz[i]);
        }
    }

    // combine the two k-halves: partner lane is lane ^ 16 (same b,n)
#pragma unroll
    for (int i = 0; i < MB; i++) {
        pdf[i] += __shfl_xor_sync(0xFFFFFFFFu, pdf[i], 16);
        gx[i]  += __shfl_xor_sync(0xFFFFFFFFu, gx[i],  16);
        gy[i]  += __shfl_xor_sync(0xFFFFFFFFu, gy[i],  16);
        gz[i]  += __shfl_xor_sync(0xFFFFFFFFu, gz[i],  16);
    }

    // epilogue: gacc = (0.5*log2e)*grad_true (positive multiple);
    // (log2e/1100)/(0.5*log2e) = 1/550 -> mag = 2^(5*log2e - |gacc|/550)
    const float L2E_OVER_TAU = 0.19235933878519513f;  // log2e / 7.5
    const float MAG_C0 = 7.2134752044448170f;         // 5 * log2 e
    const float MAG_C1 = -1.0f / 550.0f;
    float* out_grad = out + (size_t)PB * PN * 3;

    if (kh == 0) {
        // density sigmoid, lanes 0..15: contiguous 192B per (warp,i)
#pragma unroll
        for (int i = 0; i < MB; i++) {
            int b = b0 + i;
            float u = ex2a((40.0f - pdf[i]) * L2E_OVER_TAU);
            float s = rcpa(1.0f + u);
            float* od = out + ((size_t)b * PN + n) * 3;
            od[0] = s; od[1] = s; od[2] = s;
        }
    } else {
        // gradient, lanes 16..31: contiguous 192B per (warp,i)
#pragma unroll
        for (int i = 0; i < MB; i++) {
            int b = b0 + i;
            float s2 = fmaf(gx[i], gx[i], fmaf(gy[i], gy[i], gz[i] * gz[i]));
            float rinv = rsqrtf(s2);
            float gs = s2 * rinv;                    // |gacc|
            float mag = ex2a(fmaf(gs, MAG_C1, MAG_C0));
            float scale = rinv * mag;                // ETA=1; sign correct
            float* og = out_grad + ((size_t)b * PN + n) * 3;
            og[0] = gx[i] * scale;
            og[1] = gy[i] * scale;
            og[2] = gz[i] * scale;
        }
    }
}

extern "C" void kernel_launch(void* const* d_in, const int* in_sizes, int n_in,
                              void* d_out, int out_size) {
    const float* kps     = (const float*)d_in[0];
    const float* means   = (const float*)d_in[1];
    const float* covs    = (const float*)d_in[2];
    const float* weights = (const float*)d_in[3];
    float* out = (float*)d_out;

    precompute_params<<<2, 256>>>(means, covs, weights);

    int total_threads = (PB / MB) * PN * 2;     // 262144 (k split 2-way)
    gmm_main<<<total_threads / TPB, TPB>>>(kps, out);
}

// round 11
// speedup vs baseline: 1.4756x; 1.0448x over previous
#include <cuda_runtime.h>

// Problem constants
#define PB 16384   // batch
#define PN 32      // keypoints
#define PK 16      // mixture components
#define KH 8       // components per thread (K split 2 ways)
#define MB 4       // samples per thread
#define TPB 128

// Packed per-(n,k) params, SoA over n within k, idx = k*32 + n:
//  g_pab[idx]        : (-mx, -my, -mz, q00)
//  g_pab[idx + 512]  : (q01, q02, q11, q12)   (constant +8192B offset from pa)
//  g_pc[idx]         : (q22, lc)
// q = precision * (-0.5*log2e), lc = log2(w) - 0.5*log2((2pi)^3 det)
__device__ float4 g_pab[2 * PK * PN];
__device__ float2 g_pc[PK * PN];

__global__ void precompute_params(const float* __restrict__ means,
                                  const float* __restrict__ covs,
                                  const float* __restrict__ weights) {
    int t = blockIdx.x * 256 + threadIdx.x;
    if (t >= PN * PK) return;
    int n = t & 31;
    int k = t >> 5;
    int nk = n * PK + k;

    const float* c = covs + nk * 9;
    float c00 = c[0], c01 = c[1], c02 = c[2];
    float c11 = c[4], c12 = c[5], c22 = c[8];

    float m00 = c11 * c22 - c12 * c12;
    float m01 = c02 * c12 - c01 * c22;
    float m02 = c01 * c12 - c02 * c11;
    float det = c00 * m00 + c01 * m01 + c02 * m02;
    const float NH = -0.72134752044448170f;   // -(0.5*log2 e), folded into precision
    float inv = NH / det;

    const float TWOPI3 = 248.05021344239853f; // (2*pi)^3
    float lc = log2f(weights[nk]) - 0.5f * log2f(TWOPI3 * det);

    const float* mu = means + nk * 3;
    int idx = k * PN + n;
    g_pab[idx] = make_float4(-mu[0], -mu[1], -mu[2], m00 * inv);
    g_pab[idx + PK * PN] = make_float4(m01 * inv, m02 * inv,
                                       (c00 * c22 - c02 * c02) * inv,
                                       (c01 * c02 - c00 * c12) * inv);
    g_pc[idx] = make_float2((c00 * c11 - c01 * c01) * inv, lc);
}

__device__ __forceinline__ float ex2a(float x) {
    float r; asm("ex2.approx.ftz.f32 %0,%1;" : "=f"(r) : "f"(x)); return r;
}
__device__ __forceinline__ float rcpa(float x) {
    float r; asm("rcp.approx.ftz.f32 %0,%1;" : "=f"(r) : "f"(x)); return r;
}

// NO launch_bounds reg cap (R5/R7: caps -> spills -> regression).
__global__ void gmm_main(const float* __restrict__ kps,
                         float* __restrict__ out) {
    // index decode: lane = khalf*16 + n16 ; warp covers 16 consecutive n, both k-halves
    int gtid = blockIdx.x * TPB + threadIdx.x;
    int lane = gtid & 31;
    int kh   = lane >> 4;            // which half of K this thread computes
    int rest = gtid >> 5;
    int n    = ((rest & 1) << 4) | (lane & 15);
    int bg   = rest >> 1;            // 0 .. PB/MB-1
    int b0   = bg * MB;

    float x[MB], y[MB], z[MB];
#pragma unroll
    for (int i = 0; i < MB; i++) {
        const float* p = kps + ((b0 + i) * PN + n) * 3;
        x[i] = p[0]; y[i] = p[1]; z[i] = p[2];
    }

    float pdf[MB], gx[MB], gy[MB], gz[MB];
#pragma unroll
    for (int i = 0; i < MB; i++) { pdf[i] = 0.0f; gx[i] = 0.0f; gy[i] = 0.0f; gz[i] = 0.0f; }

    // base index for this thread's K half; all 8 iterations become
    // immediate offsets from two base registers after full unroll.
    const float4* pab = g_pab + (kh * (KH * PN) + n);
    const float2* pcp = g_pc  + (kh * (KH * PN) + n);

#pragma unroll
    for (int j = 0; j < KH; j++) {
        float4 pa = __ldg(pab + j * PN);            // -mx,-my,-mz,q00
        float4 pb = __ldg(pab + j * PN + PK * PN);  // q01,q02,q11,q12 (+8192B imm)
        float2 pc = __ldg(pcp + j * PN);            // q22, lc

#pragma unroll
        for (int i = 0; i < MB; i++) {
            float d0 = x[i] + pa.x;
            float d1 = y[i] + pa.y;
            float d2 = z[i] + pa.z;
            // pd = (-0.5*log2e) * Sigma^{-1}(x-mu)
            float pd0 = fmaf(pa.w, d0, fmaf(pb.x, d1, pb.y * d2));
            float pd1 = fmaf(pb.x, d0, fmaf(pb.z, d1, pb.w * d2));
            float pd2 = fmaf(pb.y, d0, fmaf(pb.w, d1, pc.x * d2));
            float earg = fmaf(pd0, d0, fmaf(pd1, d1, fmaf(pd2, d2, pc.y)));
            float e = ex2a(earg);
            pdf[i] += e;
            gx[i] = fmaf(e, pd0, gx[i]);
            gy[i] = fmaf(e, pd1, gy[i]);
            gz[i] = fmaf(e, pd2, gz[i]);
        }
    }

    // combine the two k-halves: partner lane is lane ^ 16 (same b,n)
#pragma unroll
    for (int i = 0; i < MB; i++) {
        pdf[i] += __shfl_xor_sync(0xFFFFFFFFu, pdf[i], 16);
        gx[i]  += __shfl_xor_sync(0xFFFFFFFFu, gx[i],  16);
        gy[i]  += __shfl_xor_sync(0xFFFFFFFFu, gy[i],  16);
        gz[i]  += __shfl_xor_sync(0xFFFFFFFFu, gz[i],  16);
    }

    // epilogue: gacc = (0.5*log2e)*grad_true (positive multiple);
    // (log2e/1100)/(0.5*log2e) = 1/550 -> mag = 2^(5*log2e - |gacc|/550)
    const float L2E_OVER_TAU = 0.19235933878519513f;  // log2e / 7.5
    const float MAG_C0 = 7.2134752044448170f;         // 5 * log2 e
    const float MAG_C1 = -1.0f / 550.0f;
    float* out_grad = out + (size_t)PB * PN * 3;

    if (kh == 0) {
        // density sigmoid, lanes 0..15: contiguous 192B per (warp,i)
#pragma unroll
        for (int i = 0; i < MB; i++) {
            int b = b0 + i;
            float u = ex2a((40.0f - pdf[i]) * L2E_OVER_TAU);
            float s = rcpa(1.0f + u);
            float* od = out + ((size_t)b * PN + n) * 3;
            od[0] = s; od[1] = s; od[2] = s;
        }
    } else {
        // gradient, lanes 16..31: contiguous 192B per (warp,i)
#pragma unroll
        for (int i = 0; i < MB; i++) {
            int b = b0 + i;
            float s2 = fmaf(gx[i], gx[i], fmaf(gy[i], gy[i], gz[i] * gz[i]));
            float rinv = rsqrtf(s2);
            float gs = s2 * rinv;                    // |gacc|
            float mag = ex2a(fmaf(gs, MAG_C1, MAG_C0));
            float scale = rinv * mag;                // ETA=1; sign correct
            float* og = out_grad + ((size_t)b * PN + n) * 3;
            og[0] = gx[i] * scale;
            og[1] = gy[i] * scale;
            og[2] = gz[i] * scale;
        }
    }
}

extern "C" void kernel_launch(void* const* d_in, const int* in_sizes, int n_in,
                              void* d_out, int out_size) {
    const float* kps     = (const float*)d_in[0];
    const float* means   = (const float*)d_in[1];
    const float* covs    = (const float*)d_in[2];
    const float* weights = (const float*)d_in[3];
    float* out = (float*)d_out;

    precompute_params<<<2, 256>>>(means, covs, weights);

    int total_threads = (PB / MB) * PN * 2;     // 262144 (k split 2-way)
    gmm_main<<<total_threads / TPB, TPB>>>(kps, out);
}